// round 15
// baseline (speedup 1.0000x reference)
#include <cuda_runtime.h>
#include <cuda_fp16.h>
#include <cstdint>
#include <math.h>

// ---------------- problem constants ----------------
#define BATCH      16
#define IMG_HW     3600
#define F1         256
#define F2         256
#define CONV1_H    52
#define CONV1_W    52
#define C1POS      2704
#define N1TOT      43264
#define NPOS       484
#define CAP_DIM    8
#define NUM_MAP    32
#define PP         15488
#define NCLASS     10
#define DDIM       16
#define KTOT       20736
#define NTOT       7744
#define H1N        512
#define H2N        1024
#define RECN       3600
#define KSPLIT     12
#define K1PAD      96

#define OUT_Y_OFF    0
#define OUT_REC_OFF  160
#define OUT_VL_OFF   57760

// ---------------- scratch ----------------
__device__ unsigned short g_x1h[BATCH * F1 * C1POS];
__device__ unsigned short g_w16[F2 * KTOT];
__device__ unsigned short g_w1h[F1 * K1PAD];
__device__ unsigned short g_imgh[BATCH * IMG_HW];
__device__ int      g_koff[KTOT];
__device__ float g_pcp[KSPLIT * F2 * NTOT];
__device__ uint4 g_uh[BATCH * PP];           // u fp16: one uint4 (8 halves) per capsule
__device__ float g_v [BATCH * NCLASS * DDIM];
__device__ float g_h1[BATCH * H1N];
__device__ float g_h2[BATCH * H2N];

__device__ __forceinline__ uint32_t smem_u32(const void* p) {
    uint32_t a;
    asm("{ .reg .u64 t; cvta.to.shared.u64 t, %1; cvt.u32.u64 %0, t; }" : "=r"(a) : "l"(p));
    return a;
}
__device__ __forceinline__ void cpasync16(uint32_t dst, const void* src) {
    asm volatile("cp.async.ca.shared.global [%0], [%1], 16;" :: "r"(dst), "l"(src));
}
__device__ __forceinline__ void cp_commit() {
    asm volatile("cp.async.commit_group;" ::: "memory");
}
template<int N>
__device__ __forceinline__ void cp_wait() {
    asm volatile("cp.async.wait_group %0;" :: "n"(N) : "memory");
}
__device__ __forceinline__ void ldmx4(uint32_t* r, uint32_t addr) {
    asm volatile("ldmatrix.sync.aligned.m8n8.x4.shared.b16 {%0,%1,%2,%3}, [%4];"
                 : "=r"(r[0]), "=r"(r[1]), "=r"(r[2]), "=r"(r[3]) : "r"(addr));
}
__device__ __forceinline__ void mma16816h(float* c, const uint32_t* a, const uint32_t* b) {
    asm volatile(
        "mma.sync.aligned.m16n8k16.row.col.f32.f16.f16.f32 "
        "{%0,%1,%2,%3}, {%4,%5,%6,%7}, {%8,%9}, {%0,%1,%2,%3};"
        : "+f"(c[0]), "+f"(c[1]), "+f"(c[2]), "+f"(c[3])
        : "r"(a[0]), "r"(a[1]), "r"(a[2]), "r"(a[3]), "r"(b[0]), "r"(b[1]));
}
__device__ __forceinline__ uint32_t packh2(float a, float b) {
    __half2 h = __floats2half2_rn(a, b);
    return *reinterpret_cast<uint32_t*>(&h);
}
__device__ __forceinline__ float2 unph2(uint32_t u) {
    return __half22float2(*reinterpret_cast<__half2*>(&u));
}
// evict-first store of float2 / streaming load of float4
__device__ __forceinline__ void stcs_f2(float* p, float2 v) {
    asm volatile("st.global.cs.v2.f32 [%0], {%1, %2};" :: "l"(p), "f"(v.x), "f"(v.y) : "memory");
}
__device__ __forceinline__ float4 ldcs_f4(const float* p) {
    float4 v;
    asm volatile("ld.global.cs.v4.f32 {%0, %1, %2, %3}, [%4];"
                 : "=f"(v.x), "=f"(v.y), "=f"(v.z), "=f"(v.w) : "l"(p));
    return v;
}

// ---------------- prep ----------------
__global__ __launch_bounds__(256) void wprep_kernel(
    const float* __restrict__ w, const float* __restrict__ w1,
    const float* __restrict__ img)
{
    int i = blockIdx.x * 256 + threadIdx.x;
    int i4 = i * 4;
    if (i4 < F2 * KTOT) {
        float4 v = *(const float4*)(w + i4);
        ushort4 o;
        o.x = __half_as_ushort(__float2half_rn(v.x));
        o.y = __half_as_ushort(__float2half_rn(v.y));
        o.z = __half_as_ushort(__float2half_rn(v.z));
        o.w = __half_as_ushort(__float2half_rn(v.w));
        *(ushort4*)(g_w16 + i4) = o;
    }
    if (i < KTOT) {
        int ci = i / 81, r = i - ci * 81;
        int ky = r / 9, kx = r - ky * 9;
        g_koff[i] = ci * C1POS + ky * CONV1_W + kx;
    }
    if (i < F1 * K1PAD) {
        int oc = i / K1PAD, k = i - oc * K1PAD;
        g_w1h[i] = (k < 81) ? __half_as_ushort(__float2half_rn(w1[oc * 81 + k])) : 0;
    }
    if (i < BATCH * IMG_HW)
        g_imgh[i] = __half_as_ushort(__float2half_rn(img[i]));
}

// ---------------- conv1: single-shot fp16 MMA GEMM -------------------------
#define C1_STRIDE 208
#define A1_BYTES  (256 * C1_STRIDE)
#define B1_BYTES  (64 * C1_STRIDE)

__global__ __launch_bounds__(256, 2) void conv1_mma_kernel(const float* __restrict__ bias)
{
    extern __shared__ __align__(128) char smem[];
    const uint32_t sb = smem_u32(smem);
    const int tid = threadIdx.x;
    const int lane = tid & 31;
    const int warp = tid >> 5;
    const int wm = warp & 3;
    const int wn = warp >> 2;
    const int pos0 = blockIdx.x * 64;

    {
        const unsigned short* src = g_w1h + (size_t)tid * K1PAD;
        uint32_t d = sb + tid * C1_STRIDE;
#pragma unroll
        for (int q = 0; q < 12; q++)
            cpasync16(d + q * 16, src + q * 8);
        cp_commit();
    }
    {
        const int brow = tid & 63;
        const int kq = tid >> 6;
        int n = pos0 + brow;
        int b = n / C1POS, r = n - b * C1POS;
        int oy = r / CONV1_W, ox = r - oy * CONV1_W;
        const unsigned short* ib = g_imgh + b * IMG_HW + oy * 60 + ox;
        unsigned short* dst = (unsigned short*)(smem + A1_BYTES + brow * C1_STRIDE) + kq * 24;
#pragma unroll
        for (int k = 0; k < 24; k++) {
            int kg = kq * 24 + k;
            unsigned short v = 0;
            if (kg < 81) {
                int ky = kg / 9, kx = kg - ky * 9;
                v = ib[ky * 60 + kx];
            }
            dst[k] = v;
        }
    }
    cp_wait<0>();
    __syncthreads();

    float acc[4][4][4];
#pragma unroll
    for (int i = 0; i < 4; i++)
#pragma unroll
        for (int j = 0; j < 4; j++)
#pragma unroll
            for (int q = 0; q < 4; q++) acc[i][j][q] = 0.f;

    const uint32_t a_row = (uint32_t)(wm * 64 + (lane & 15));
    const uint32_t a_koff = (uint32_t)((lane >> 4) * 16);
    const uint32_t b_row_base = (uint32_t)(wn * 32 + ((lane >> 4) & 1) * 8 + (lane & 7));
    const uint32_t b_koff = (uint32_t)(((lane >> 3) & 1) * 16);
    const uint32_t a_base = sb;
    const uint32_t b_base = sb + A1_BYTES;

#pragma unroll
    for (int kk = 0; kk < 6; kk++) {
        uint32_t a_f[4][4], b_f[2][4];
#pragma unroll
        for (int mt = 0; mt < 4; mt++)
            ldmx4(a_f[mt], a_base + (a_row + mt * 16) * C1_STRIDE + kk * 32 + a_koff);
#pragma unroll
        for (int nt2 = 0; nt2 < 2; nt2++)
            ldmx4(b_f[nt2], b_base + (b_row_base + nt2 * 16) * C1_STRIDE + kk * 32 + b_koff);
#pragma unroll
        for (int mt = 0; mt < 4; mt++)
#pragma unroll
            for (int nt = 0; nt < 4; nt++)
                mma16816h(acc[mt][nt], a_f[mt], &b_f[nt >> 1][(nt & 1) * 2]);
    }

    const int g = lane >> 2, t0 = lane & 3;
#pragma unroll
    for (int mt = 0; mt < 4; mt++) {
        int oc0 = wm * 64 + mt * 16 + g;
        float bia0 = bias[oc0], bia1 = bias[oc0 + 8];
#pragma unroll
        for (int nt = 0; nt < 4; nt++) {
            int n0 = pos0 + wn * 32 + nt * 8 + 2 * t0;
#pragma unroll
            for (int e = 0; e < 2; e++) {
                int n = n0 + e;
                int b = n / C1POS, r = n - b * C1POS;
                size_t base = (size_t)b * F1 * C1POS + r;
                g_x1h[base + (size_t)oc0 * C1POS] =
                    __half_as_ushort(__float2half_rn(fmaxf(acc[mt][nt][e] + bia0, 0.f)));
                g_x1h[base + (size_t)(oc0 + 8) * C1POS] =
                    __half_as_ushort(__float2half_rn(fmaxf(acc[mt][nt][2 + e] + bia1, 0.f)));
            }
        }
    }
}

// ---------------- pconv: single-pass fp16 mma.sync, 12-way K-split ---------
#define BK        32
#define NST       3
#define A_STRIDE  80
#define A_BYTES   (256 * A_STRIDE)
#define B_BYTES   (64 * A_STRIDE)
#define STG       (A_BYTES + B_BYTES)
#define NCHUNK    (KTOT / BK)
#define CPS       (NCHUNK / KSPLIT)             // 54

__global__ __launch_bounds__(256, 2) void pconv_mma_kernel()
{
    extern __shared__ __align__(128) char smem[];
    const uint32_t sb = smem_u32(smem);
    const int tid = threadIdx.x;
    const int lane = tid & 31;
    const int warp = tid >> 5;
    const int wm = warp & 3;
    const int wn = warp >> 2;
    const int pos0 = blockIdx.x * 64;
    const int ks   = blockIdx.y;
    const int cbase = ks * CPS;

    const int brow = tid & 63;
    const int bkq  = tid >> 6;
    int nb;
    {
        int n = pos0 + brow;
        int bb = n / NPOS, pos = n - bb * NPOS;
        int oy = pos / 22, ox = pos - oy * 22;
        nb = bb * (F1 * C1POS) + oy * (2 * CONV1_W) + ox * 2;
    }

    float acc[4][4][4];
#pragma unroll
    for (int i = 0; i < 4; i++)
#pragma unroll
        for (int j = 0; j < 4; j++)
#pragma unroll
            for (int q = 0; q < 4; q++) acc[i][j][q] = 0.f;

    auto load_chunk = [&](int s, int i) {
        const int kc = (cbase + i) * BK;
        {
            const unsigned short* src = g_w16 + (size_t)tid * KTOT + kc;
            uint32_t dh = sb + s * STG + tid * A_STRIDE;
#pragma unroll
            for (int q = 0; q < 4; q++)
                cpasync16(dh + q * 16, src + q * 8);
        }
        {
            const int* ko = g_koff + kc + bkq * 8;
            int4 k0 = ((const int4*)ko)[0];
            int4 k1 = ((const int4*)ko)[1];
            unsigned p0 = __ldg(&g_x1h[nb + k0.x]);
            unsigned p1 = __ldg(&g_x1h[nb + k0.y]);
            unsigned p2 = __ldg(&g_x1h[nb + k0.z]);
            unsigned p3 = __ldg(&g_x1h[nb + k0.w]);
            unsigned p4 = __ldg(&g_x1h[nb + k1.x]);
            unsigned p5 = __ldg(&g_x1h[nb + k1.y]);
            unsigned p6 = __ldg(&g_x1h[nb + k1.z]);
            unsigned p7 = __ldg(&g_x1h[nb + k1.w]);
            uint4 v = make_uint4(p0 | (p1 << 16), p2 | (p3 << 16),
                                 p4 | (p5 << 16), p6 | (p7 << 16));
            uint32_t db = s * STG + A_BYTES + brow * A_STRIDE + bkq * 16;
            *(uint4*)(smem + db) = v;
        }
    };

#pragma unroll
    for (int s = 0; s < NST - 1; s++) {
        load_chunk(s, s);
        cp_commit();
    }

    const uint32_t a_row = (uint32_t)(wm * 64 + (lane & 15));
    const uint32_t a_koff = (uint32_t)((lane >> 4) * 16);
    const uint32_t b_row_base = (uint32_t)(wn * 32 + ((lane >> 4) & 1) * 8 + (lane & 7));
    const uint32_t b_koff = (uint32_t)(((lane >> 3) & 1) * 16);

    for (int i = 0; i < CPS; i++) {
        cp_wait<NST - 2>();
        __syncthreads();
        const int s = i % NST;
        const uint32_t a_base = sb + s * STG;
        const uint32_t b_base = a_base + A_BYTES;

#pragma unroll
        for (int kk = 0; kk < 2; kk++) {
            uint32_t a_f[4][4], b_f[2][4];
#pragma unroll
            for (int mt = 0; mt < 4; mt++)
                ldmx4(a_f[mt], a_base + (a_row + mt * 16) * A_STRIDE + kk * 32 + a_koff);
#pragma unroll
            for (int nt2 = 0; nt2 < 2; nt2++)
                ldmx4(b_f[nt2], b_base + (b_row_base + nt2 * 16) * A_STRIDE + kk * 32 + b_koff);
#pragma unroll
            for (int mt = 0; mt < 4; mt++)
#pragma unroll
                for (int nt = 0; nt < 4; nt++)
                    mma16816h(acc[mt][nt], a_f[mt], &b_f[nt >> 1][(nt & 1) * 2]);
        }
        int nx = i + NST - 1;
        if (nx < CPS) load_chunk(nx % NST, nx);
        cp_commit();
    }

    // epilogue: evict-first partial stores (keep x1h resident in L2)
    const int g = lane >> 2, t0 = lane & 3;
#pragma unroll
    for (int mt = 0; mt < 4; mt++) {
        int oc0 = wm * 64 + mt * 16 + g;
#pragma unroll
        for (int nt = 0; nt < 4; nt++) {
            int n0 = pos0 + wn * 32 + nt * 8 + 2 * t0;
            float* d0 = g_pcp + ((size_t)ks * F2 + oc0) * NTOT + n0;
            stcs_f2(d0, make_float2(acc[mt][nt][0], acc[mt][nt][1]));
            stcs_f2(d0 + (size_t)8 * NTOT, make_float2(acc[mt][nt][2], acc[mt][nt][3]));
        }
    }
}

// ---------------- fused K-combine + squash -> u fp16, 4 caps/thread --------
__global__ __launch_bounds__(256) void usquash_kernel(const float* __restrict__ bias)
{
    int t = blockIdx.x * 256 + threadIdx.x;
    if (t >= BATCH * PP / 4) return;
    int cap = t * 4;
    int b = cap / PP, p = cap - b * PP;
    int mm = p / NPOS, pos = p - mm * NPOS;
    int n = b * NPOS + pos;

    float uu[8][4];
    float sq[4] = {0.f, 0.f, 0.f, 0.f};
#pragma unroll
    for (int e = 0; e < 8; e++) {
        int oc = e * NUM_MAP + mm;
        const float* q = g_pcp + (size_t)oc * NTOT + n;
        float bia = bias[oc];
        float a0 = bia, a1 = bia, a2 = bia, a3 = bia;
#pragma unroll
        for (int s = 0; s < KSPLIT; s++) {
            float4 v = ldcs_f4(q + (size_t)s * F2 * NTOT);
            a0 += v.x; a1 += v.y; a2 += v.z; a3 += v.w;
        }
        uu[e][0] = a0; uu[e][1] = a1; uu[e][2] = a2; uu[e][3] = a3;
        sq[0] += a0 * a0; sq[1] += a1 * a1; sq[2] += a2 * a2; sq[3] += a3 * a3;
    }
#pragma unroll
    for (int j = 0; j < 4; j++) {
        float sc = (sq[j] / (1.f + sq[j])) * rsqrtf(sq[j] + 1e-8f);
        g_uh[cap + j] = make_uint4(
            packh2(uu[0][j] * sc, uu[1][j] * sc), packh2(uu[2][j] * sc, uu[3][j] * sc),
            packh2(uu[4][j] * sc, uu[5][j] * sc), packh2(uu[6][j] * sc, uu[7][j] * sc));
    }
}

// ---------------- routing: all 3 iterations fused in one kernel ------------
__global__ __launch_bounds__(1024) void routing_all(const float* __restrict__ Wd)
{
    const int bc = blockIdx.x;
    const int b = bc / NCLASS, c = bc - b * NCLASS;
    const int tid = threadIdx.x;
    const int lane = tid & 31, wid = tid >> 5;
    __shared__ float swarp[32][10];
    __shared__ float sres[9];
    __shared__ float sv16[16];
    __shared__ float sscale;
    __shared__ float swv[8];

    if (tid < 8) swv[tid] = 0.f;
    __syncthreads();

    const uint4* up = g_uh + (size_t)b * PP;
    float w0 = 0, w1 = 0, w2v = 0, w3 = 0, w4 = 0, w5 = 0, w6 = 0, w7 = 0;

    for (int it = 0; it < 3; it++) {
        float vals[9];
#pragma unroll
        for (int r = 0; r < 9; r++) vals[r] = 0.f;
        for (int p = tid; p < PP; p += 1024) {
            uint4 q = up[p];
            float2 f0 = unph2(q.x), f1 = unph2(q.y), f2 = unph2(q.z), f3 = unph2(q.w);
            float wgt;
            if (it == 0) wgt = 1.f;
            else {
                float d = f0.x*w0 + f0.y*w1 + f1.x*w2v + f1.y*w3
                        + f2.x*w4 + f2.y*w5 + f3.x*w6 + f3.y*w7;
                wgt = __expf(d);
            }
            vals[0] += wgt;
            vals[1] += wgt * f0.x; vals[2] += wgt * f0.y;
            vals[3] += wgt * f1.x; vals[4] += wgt * f1.y;
            vals[5] += wgt * f2.x; vals[6] += wgt * f2.y;
            vals[7] += wgt * f3.x; vals[8] += wgt * f3.y;
        }
#pragma unroll
        for (int r = 0; r < 9; r++)
#pragma unroll
            for (int off = 16; off > 0; off >>= 1)
                vals[r] += __shfl_xor_sync(0xffffffffu, vals[r], off);
        if (lane == 0)
#pragma unroll
            for (int r = 0; r < 9; r++) swarp[wid][r] = vals[r];
        __syncthreads();
        if (tid < 9) {
            float s = 0.f;
            for (int q = 0; q < 32; q++) s += swarp[q][tid];
            sres[tid] = s;
        }
        __syncthreads();

        const float Zt = sres[0];
        if (tid < DDIM) {
            float s = 0.f;
#pragma unroll
            for (int e = 0; e < 8; e++)
                s += Wd[(c * DDIM + tid) * 8 + e] * (sres[1 + e] / Zt);
            sv16[tid] = s;
        }
        __syncthreads();
        if (tid == 0) {
            float sq = 0.f;
#pragma unroll
            for (int d = 0; d < DDIM; d++) sq += sv16[d] * sv16[d];
            sscale = (sq / (1.f + sq)) * rsqrtf(sq + 1e-8f);
        }
        __syncthreads();
        if (tid < DDIM) {
            float vd = sv16[tid] * sscale;
            sv16[tid] = vd;
            if (it == 2) g_v[bc * DDIM + tid] = vd;
        }
        __syncthreads();
        if (it < 2) {
            if (tid < CAP_DIM) {
                float acc = 0.f;
#pragma unroll
                for (int d = 0; d < DDIM; d++)
                    acc += Wd[(c * DDIM + d) * 8 + tid] * sv16[d];
                swv[tid] += acc;
            }
            __syncthreads();
            w0 = swv[0]; w1 = swv[1]; w2v = swv[2]; w3 = swv[3];
            w4 = swv[4]; w5 = swv[5]; w6 = swv[6]; w7 = swv[7];
            __syncthreads();
        }
    }
}

// ---------------- decoder: dec1 builds mask + writes y_ohe/v_len -----------
__global__ __launch_bounds__(256) void dec1_kernel(
    const float* __restrict__ w, const float* __restrict__ bias,
    float* __restrict__ out)
{
    const int tid = threadIdx.x;
    int g = blockIdx.x * 256 + tid;
    int b = g >> 9, j = g & 511;
    __shared__ float sm[160];
    __shared__ float svl[NCLASS];
    __shared__ int spred;
    if (tid < NCLASS) {
        float sq = 0.f;
#pragma unroll
        for (int d = 0; d < DDIM; d++) {
            float vv = g_v[(b * NCLASS + tid) * DDIM + d];
            sq += vv * vv;
        }
        svl[tid] = sq;
    }
    __syncthreads();
    if (tid == 0) {
        int pm = 0; float best = svl[0];
        for (int c = 1; c < NCLASS; c++)
            if (svl[c] > best) { best = svl[c]; pm = c; }
        spred = pm;
    }
    __syncthreads();
    // even block of each batch also emits y_ohe + v_len (finalize merged)
    if (!(blockIdx.x & 1) && tid < NCLASS) {
        out[OUT_Y_OFF + b * NCLASS + tid] = (tid == spred) ? 1.0f : 0.0f;
        out[OUT_VL_OFF + b * NCLASS + tid] = sqrtf(svl[tid]);
    }
    if (tid < 160) {
        int c = tid >> 4, d = tid & 15;
        sm[tid] = (c == spred) ? g_v[(b * NCLASS + c) * DDIM + d] : 0.f;
    }
    __syncthreads();

    float acc = bias[j];
#pragma unroll 8
    for (int i = 0; i < 160; i++)
        acc += sm[i] * w[i * H1N + j];
    g_h1[g] = fmaxf(acc, 0.f);
}

__global__ __launch_bounds__(256) void dec2_kernel(
    const float* __restrict__ w, const float* __restrict__ bias)
{
    int g = blockIdx.x * 256 + threadIdx.x;
    int b = g >> 10, j = g & 1023;
    float acc = bias[j];
#pragma unroll 8
    for (int i = 0; i < H1N; i++)
        acc += g_h1[b * H1N + i] * w[i * H2N + j];
    g_h2[g] = fmaxf(acc, 0.f);
}

__global__ __launch_bounds__(256) void dec3_kernel(
    const float* __restrict__ w, const float* __restrict__ bias,
    float* __restrict__ out)
{
    int jl = threadIdx.x >> 4, b = threadIdx.x & 15;
    int j = blockIdx.x * 16 + jl;
    float acc = bias[j];
#pragma unroll 8
    for (int i = 0; i < H2N; i++)
        acc += g_h2[b * H2N + i] * w[i * RECN + j];
    out[OUT_REC_OFF + b * RECN + j] = 1.f / (1.f + expf(-acc));
}

// ---------------- launch ----------------
extern "C" void kernel_launch(void* const* d_in, const int* in_sizes, int n_in,
                              void* d_out, int out_size)
{
    const float* imgs    = (const float*)d_in[0];
    const float* conv1_w = (const float*)d_in[1];
    const float* conv1_b = (const float*)d_in[2];
    const float* pconv_w = (const float*)d_in[3];
    const float* pconv_b = (const float*)d_in[4];
    const float* W_digit = (const float*)d_in[5];
    const float* dec_w1  = (const float*)d_in[6];
    const float* dec_b1  = (const float*)d_in[7];
    const float* dec_w2  = (const float*)d_in[8];
    const float* dec_b2  = (const float*)d_in[9];
    const float* dec_w3  = (const float*)d_in[10];
    const float* dec_b3  = (const float*)d_in[11];
    float* out = (float*)d_out;

    const int smem_p = NST * STG;
    cudaFuncSetAttribute(pconv_mma_kernel,
                         cudaFuncAttributeMaxDynamicSharedMemorySize, smem_p);
    const int smem_c1 = A1_BYTES + B1_BYTES;
    cudaFuncSetAttribute(conv1_mma_kernel,
                         cudaFuncAttributeMaxDynamicSharedMemorySize, smem_c1);

    wprep_kernel<<<(F2 * KTOT / 4 + 255) / 256, 256>>>(pconv_w, conv1_w, imgs);
    conv1_mma_kernel<<<N1TOT / 64, 256, smem_c1>>>(conv1_b);
    pconv_mma_kernel<<<dim3(NTOT / 64, KSPLIT), 256, smem_p>>>();
    usquash_kernel<<<(BATCH * PP / 4 + 255) / 256, 256>>>(pconv_b);

    routing_all<<<BATCH * NCLASS, 1024>>>(W_digit);

    dec1_kernel<<<(BATCH * H1N) / 256, 256>>>(dec_w1, dec_b1, out);
    dec2_kernel<<<(BATCH * H2N) / 256, 256>>>(dec_w2, dec_b2);
    dec3_kernel<<<RECN / 16, 256>>>(dec_w3, dec_b3, out);
}

// round 16
// speedup vs baseline: 1.5295x; 1.5295x over previous
#include <cuda_runtime.h>
#include <cuda_fp16.h>
#include <cstdint>
#include <math.h>

// ---------------- problem constants ----------------
#define BATCH      16
#define IMG_HW     3600
#define F1         256
#define F2         256
#define CONV1_H    52
#define CONV1_W    52
#define C1POS      2704
#define N1TOT      43264
#define NPOS       484
#define CAP_DIM    8
#define NUM_MAP    32
#define PP         15488
#define NCLASS     10
#define DDIM       16
#define KTOT       20736
#define NTOT       7744
#define H1N        512
#define H2N        1024
#define RECN       3600
#define KSPLIT     12
#define K1PAD      96

#define OUT_Y_OFF    0
#define OUT_REC_OFF  160
#define OUT_VL_OFF   57760

// ---------------- scratch ----------------
__device__ unsigned short g_x1h[BATCH * F1 * C1POS];
__device__ unsigned short g_w16[F2 * KTOT];
__device__ unsigned short g_w1h[F1 * K1PAD];
__device__ unsigned short g_imgh[BATCH * IMG_HW];
__device__ int      g_koff[KTOT];
__device__ float g_pcp[KSPLIT * F2 * NTOT];
__device__ uint4 g_uh[BATCH * PP];           // u fp16: one uint4 (8 halves) per capsule
__device__ float g_v [BATCH * NCLASS * DDIM];
__device__ float g_h1[BATCH * H1N];
__device__ float g_h2[BATCH * H2N];

__device__ __forceinline__ uint32_t smem_u32(const void* p) {
    uint32_t a;
    asm("{ .reg .u64 t; cvta.to.shared.u64 t, %1; cvt.u32.u64 %0, t; }" : "=r"(a) : "l"(p));
    return a;
}
__device__ __forceinline__ void cpasync16(uint32_t dst, const void* src) {
    asm volatile("cp.async.ca.shared.global [%0], [%1], 16;" :: "r"(dst), "l"(src));
}
__device__ __forceinline__ void cp_commit() {
    asm volatile("cp.async.commit_group;" ::: "memory");
}
template<int N>
__device__ __forceinline__ void cp_wait() {
    asm volatile("cp.async.wait_group %0;" :: "n"(N) : "memory");
}
__device__ __forceinline__ void ldmx4(uint32_t* r, uint32_t addr) {
    asm volatile("ldmatrix.sync.aligned.m8n8.x4.shared.b16 {%0,%1,%2,%3}, [%4];"
                 : "=r"(r[0]), "=r"(r[1]), "=r"(r[2]), "=r"(r[3]) : "r"(addr));
}
__device__ __forceinline__ void mma16816h(float* c, const uint32_t* a, const uint32_t* b) {
    asm volatile(
        "mma.sync.aligned.m16n8k16.row.col.f32.f16.f16.f32 "
        "{%0,%1,%2,%3}, {%4,%5,%6,%7}, {%8,%9}, {%0,%1,%2,%3};"
        : "+f"(c[0]), "+f"(c[1]), "+f"(c[2]), "+f"(c[3])
        : "r"(a[0]), "r"(a[1]), "r"(a[2]), "r"(a[3]), "r"(b[0]), "r"(b[1]));
}
__device__ __forceinline__ uint32_t packh2(float a, float b) {
    __half2 h = __floats2half2_rn(a, b);
    return *reinterpret_cast<uint32_t*>(&h);
}
__device__ __forceinline__ float2 unph2(uint32_t u) {
    return __half22float2(*reinterpret_cast<__half2*>(&u));
}

// ---------------- prep ----------------
__global__ __launch_bounds__(256) void wprep_kernel(
    const float* __restrict__ w, const float* __restrict__ w1,
    const float* __restrict__ img)
{
    int i = blockIdx.x * 256 + threadIdx.x;
    int i4 = i * 4;
    if (i4 < F2 * KTOT) {
        float4 v = *(const float4*)(w + i4);
        ushort4 o;
        o.x = __half_as_ushort(__float2half_rn(v.x));
        o.y = __half_as_ushort(__float2half_rn(v.y));
        o.z = __half_as_ushort(__float2half_rn(v.z));
        o.w = __half_as_ushort(__float2half_rn(v.w));
        *(ushort4*)(g_w16 + i4) = o;
    }
    if (i < KTOT) {
        int ci = i / 81, r = i - ci * 81;
        int ky = r / 9, kx = r - ky * 9;
        g_koff[i] = ci * C1POS + ky * CONV1_W + kx;
    }
    if (i < F1 * K1PAD) {
        int oc = i / K1PAD, k = i - oc * K1PAD;
        g_w1h[i] = (k < 81) ? __half_as_ushort(__float2half_rn(w1[oc * 81 + k])) : 0;
    }
    if (i < BATCH * IMG_HW)
        g_imgh[i] = __half_as_ushort(__float2half_rn(img[i]));
}

// ---------------- conv1: single-shot fp16 MMA GEMM -------------------------
#define C1_STRIDE 208
#define A1_BYTES  (256 * C1_STRIDE)
#define B1_BYTES  (64 * C1_STRIDE)

__global__ __launch_bounds__(256, 2) void conv1_mma_kernel(const float* __restrict__ bias)
{
    extern __shared__ __align__(128) char smem[];
    const uint32_t sb = smem_u32(smem);
    const int tid = threadIdx.x;
    const int lane = tid & 31;
    const int warp = tid >> 5;
    const int wm = warp & 3;
    const int wn = warp >> 2;
    const int pos0 = blockIdx.x * 64;

    {
        const unsigned short* src = g_w1h + (size_t)tid * K1PAD;
        uint32_t d = sb + tid * C1_STRIDE;
#pragma unroll
        for (int q = 0; q < 12; q++)
            cpasync16(d + q * 16, src + q * 8);
        cp_commit();
    }
    {
        const int brow = tid & 63;
        const int kq = tid >> 6;
        int n = pos0 + brow;
        int b = n / C1POS, r = n - b * C1POS;
        int oy = r / CONV1_W, ox = r - oy * CONV1_W;
        const unsigned short* ib = g_imgh + b * IMG_HW + oy * 60 + ox;
        unsigned short* dst = (unsigned short*)(smem + A1_BYTES + brow * C1_STRIDE) + kq * 24;
#pragma unroll
        for (int k = 0; k < 24; k++) {
            int kg = kq * 24 + k;
            unsigned short v = 0;
            if (kg < 81) {
                int ky = kg / 9, kx = kg - ky * 9;
                v = ib[ky * 60 + kx];
            }
            dst[k] = v;
        }
    }
    cp_wait<0>();
    __syncthreads();

    float acc[4][4][4];
#pragma unroll
    for (int i = 0; i < 4; i++)
#pragma unroll
        for (int j = 0; j < 4; j++)
#pragma unroll
            for (int q = 0; q < 4; q++) acc[i][j][q] = 0.f;

    const uint32_t a_row = (uint32_t)(wm * 64 + (lane & 15));
    const uint32_t a_koff = (uint32_t)((lane >> 4) * 16);
    const uint32_t b_row_base = (uint32_t)(wn * 32 + ((lane >> 4) & 1) * 8 + (lane & 7));
    const uint32_t b_koff = (uint32_t)(((lane >> 3) & 1) * 16);
    const uint32_t a_base = sb;
    const uint32_t b_base = sb + A1_BYTES;

#pragma unroll
    for (int kk = 0; kk < 6; kk++) {
        uint32_t a_f[4][4], b_f[2][4];
#pragma unroll
        for (int mt = 0; mt < 4; mt++)
            ldmx4(a_f[mt], a_base + (a_row + mt * 16) * C1_STRIDE + kk * 32 + a_koff);
#pragma unroll
        for (int nt2 = 0; nt2 < 2; nt2++)
            ldmx4(b_f[nt2], b_base + (b_row_base + nt2 * 16) * C1_STRIDE + kk * 32 + b_koff);
#pragma unroll
        for (int mt = 0; mt < 4; mt++)
#pragma unroll
            for (int nt = 0; nt < 4; nt++)
                mma16816h(acc[mt][nt], a_f[mt], &b_f[nt >> 1][(nt & 1) * 2]);
    }

    const int g = lane >> 2, t0 = lane & 3;
#pragma unroll
    for (int mt = 0; mt < 4; mt++) {
        int oc0 = wm * 64 + mt * 16 + g;
        float bia0 = bias[oc0], bia1 = bias[oc0 + 8];
#pragma unroll
        for (int nt = 0; nt < 4; nt++) {
            int n0 = pos0 + wn * 32 + nt * 8 + 2 * t0;
#pragma unroll
            for (int e = 0; e < 2; e++) {
                int n = n0 + e;
                int b = n / C1POS, r = n - b * C1POS;
                size_t base = (size_t)b * F1 * C1POS + r;
                g_x1h[base + (size_t)oc0 * C1POS] =
                    __half_as_ushort(__float2half_rn(fmaxf(acc[mt][nt][e] + bia0, 0.f)));
                g_x1h[base + (size_t)(oc0 + 8) * C1POS] =
                    __half_as_ushort(__float2half_rn(fmaxf(acc[mt][nt][2 + e] + bia1, 0.f)));
            }
        }
    }
}

// ---------------- pconv: single-pass fp16 mma.sync, 12-way K-split ---------
#define BK        32
#define NST       3
#define A_STRIDE  80
#define A_BYTES   (256 * A_STRIDE)
#define B_BYTES   (64 * A_STRIDE)
#define STG       (A_BYTES + B_BYTES)
#define NCHUNK    (KTOT / BK)
#define CPS       (NCHUNK / KSPLIT)             // 54

__global__ __launch_bounds__(256, 2) void pconv_mma_kernel()
{
    extern __shared__ __align__(128) char smem[];
    const uint32_t sb = smem_u32(smem);
    const int tid = threadIdx.x;
    const int lane = tid & 31;
    const int warp = tid >> 5;
    const int wm = warp & 3;
    const int wn = warp >> 2;
    const int pos0 = blockIdx.x * 64;
    const int ks   = blockIdx.y;
    const int cbase = ks * CPS;

    const int brow = tid & 63;
    const int bkq  = tid >> 6;
    int nb;
    {
        int n = pos0 + brow;
        int bb = n / NPOS, pos = n - bb * NPOS;
        int oy = pos / 22, ox = pos - oy * 22;
        nb = bb * (F1 * C1POS) + oy * (2 * CONV1_W) + ox * 2;
    }

    float acc[4][4][4];
#pragma unroll
    for (int i = 0; i < 4; i++)
#pragma unroll
        for (int j = 0; j < 4; j++)
#pragma unroll
            for (int q = 0; q < 4; q++) acc[i][j][q] = 0.f;

    auto load_chunk = [&](int s, int i) {
        const int kc = (cbase + i) * BK;
        {
            const unsigned short* src = g_w16 + (size_t)tid * KTOT + kc;
            uint32_t dh = sb + s * STG + tid * A_STRIDE;
#pragma unroll
            for (int q = 0; q < 4; q++)
                cpasync16(dh + q * 16, src + q * 8);
        }
        {
            const int* ko = g_koff + kc + bkq * 8;
            int4 k0 = ((const int4*)ko)[0];
            int4 k1 = ((const int4*)ko)[1];
            unsigned p0 = __ldg(&g_x1h[nb + k0.x]);
            unsigned p1 = __ldg(&g_x1h[nb + k0.y]);
            unsigned p2 = __ldg(&g_x1h[nb + k0.z]);
            unsigned p3 = __ldg(&g_x1h[nb + k0.w]);
            unsigned p4 = __ldg(&g_x1h[nb + k1.x]);
            unsigned p5 = __ldg(&g_x1h[nb + k1.y]);
            unsigned p6 = __ldg(&g_x1h[nb + k1.z]);
            unsigned p7 = __ldg(&g_x1h[nb + k1.w]);
            uint4 v = make_uint4(p0 | (p1 << 16), p2 | (p3 << 16),
                                 p4 | (p5 << 16), p6 | (p7 << 16));
            uint32_t db = s * STG + A_BYTES + brow * A_STRIDE + bkq * 16;
            *(uint4*)(smem + db) = v;
        }
    };

#pragma unroll
    for (int s = 0; s < NST - 1; s++) {
        load_chunk(s, s);
        cp_commit();
    }

    const uint32_t a_row = (uint32_t)(wm * 64 + (lane & 15));
    const uint32_t a_koff = (uint32_t)((lane >> 4) * 16);
    const uint32_t b_row_base = (uint32_t)(wn * 32 + ((lane >> 4) & 1) * 8 + (lane & 7));
    const uint32_t b_koff = (uint32_t)(((lane >> 3) & 1) * 16);

    for (int i = 0; i < CPS; i++) {
        cp_wait<NST - 2>();
        __syncthreads();
        const int s = i % NST;
        const uint32_t a_base = sb + s * STG;
        const uint32_t b_base = a_base + A_BYTES;

#pragma unroll
        for (int kk = 0; kk < 2; kk++) {
            uint32_t a_f[4][4], b_f[2][4];
#pragma unroll
            for (int mt = 0; mt < 4; mt++)
                ldmx4(a_f[mt], a_base + (a_row + mt * 16) * A_STRIDE + kk * 32 + a_koff);
#pragma unroll
            for (int nt2 = 0; nt2 < 2; nt2++)
                ldmx4(b_f[nt2], b_base + (b_row_base + nt2 * 16) * A_STRIDE + kk * 32 + b_koff);
#pragma unroll
            for (int mt = 0; mt < 4; mt++)
#pragma unroll
                for (int nt = 0; nt < 4; nt++)
                    mma16816h(acc[mt][nt], a_f[mt], &b_f[nt >> 1][(nt & 1) * 2]);
        }
        int nx = i + NST - 1;
        if (nx < CPS) load_chunk(nx % NST, nx);
        cp_commit();
    }

    const int g = lane >> 2, t0 = lane & 3;
#pragma unroll
    for (int mt = 0; mt < 4; mt++) {
        int oc0 = wm * 64 + mt * 16 + g;
#pragma unroll
        for (int nt = 0; nt < 4; nt++) {
            int n0 = pos0 + wn * 32 + nt * 8 + 2 * t0;
            float* d0 = g_pcp + ((size_t)ks * F2 + oc0) * NTOT + n0;
            *(float2*)d0 = make_float2(acc[mt][nt][0], acc[mt][nt][1]);
            *(float2*)(d0 + (size_t)8 * NTOT) = make_float2(acc[mt][nt][2], acc[mt][nt][3]);
        }
    }
}

// ---------------- fused K-combine + squash -> u fp16, 4 caps/thread --------
__global__ __launch_bounds__(256) void usquash_kernel(const float* __restrict__ bias)
{
    int t = blockIdx.x * 256 + threadIdx.x;
    if (t >= BATCH * PP / 4) return;
    int cap = t * 4;
    int b = cap / PP, p = cap - b * PP;
    int mm = p / NPOS, pos = p - mm * NPOS;
    int n = b * NPOS + pos;

    float uu[8][4];
    float sq[4] = {0.f, 0.f, 0.f, 0.f};
#pragma unroll
    for (int e = 0; e < 8; e++) {
        int oc = e * NUM_MAP + mm;
        const float* q = g_pcp + (size_t)oc * NTOT + n;
        float bia = bias[oc];
        float a0 = bia, a1 = bia, a2 = bia, a3 = bia;
#pragma unroll
        for (int s = 0; s < KSPLIT; s++) {
            float4 v = *(const float4*)(q + (size_t)s * F2 * NTOT);
            a0 += v.x; a1 += v.y; a2 += v.z; a3 += v.w;
        }
        uu[e][0] = a0; uu[e][1] = a1; uu[e][2] = a2; uu[e][3] = a3;
        sq[0] += a0 * a0; sq[1] += a1 * a1; sq[2] += a2 * a2; sq[3] += a3 * a3;
    }
#pragma unroll
    for (int j = 0; j < 4; j++) {
        float sc = (sq[j] / (1.f + sq[j])) * rsqrtf(sq[j] + 1e-8f);
        g_uh[cap + j] = make_uint4(
            packh2(uu[0][j] * sc, uu[1][j] * sc), packh2(uu[2][j] * sc, uu[3][j] * sc),
            packh2(uu[4][j] * sc, uu[5][j] * sc), packh2(uu[6][j] * sc, uu[7][j] * sc));
    }
}

// ---------------- routing: all 3 iterations fused in one kernel ------------
__global__ __launch_bounds__(1024) void routing_all(const float* __restrict__ Wd)
{
    const int bc = blockIdx.x;
    const int b = bc / NCLASS, c = bc - b * NCLASS;
    const int tid = threadIdx.x;
    const int lane = tid & 31, wid = tid >> 5;
    __shared__ float swarp[32][10];
    __shared__ float sres[9];
    __shared__ float sv16[16];
    __shared__ float sscale;
    __shared__ float swv[8];

    if (tid < 8) swv[tid] = 0.f;
    __syncthreads();

    const uint4* up = g_uh + (size_t)b * PP;
    float w0 = 0, w1 = 0, w2v = 0, w3 = 0, w4 = 0, w5 = 0, w6 = 0, w7 = 0;

    for (int it = 0; it < 3; it++) {
        float vals[9];
#pragma unroll
        for (int r = 0; r < 9; r++) vals[r] = 0.f;
        for (int p = tid; p < PP; p += 1024) {
            uint4 q = up[p];
            float2 f0 = unph2(q.x), f1 = unph2(q.y), f2 = unph2(q.z), f3 = unph2(q.w);
            float wgt;
            if (it == 0) wgt = 1.f;
            else {
                float d = f0.x*w0 + f0.y*w1 + f1.x*w2v + f1.y*w3
                        + f2.x*w4 + f2.y*w5 + f3.x*w6 + f3.y*w7;
                wgt = __expf(d);
            }
            vals[0] += wgt;
            vals[1] += wgt * f0.x; vals[2] += wgt * f0.y;
            vals[3] += wgt * f1.x; vals[4] += wgt * f1.y;
            vals[5] += wgt * f2.x; vals[6] += wgt * f2.y;
            vals[7] += wgt * f3.x; vals[8] += wgt * f3.y;
        }
#pragma unroll
        for (int r = 0; r < 9; r++)
#pragma unroll
            for (int off = 16; off > 0; off >>= 1)
                vals[r] += __shfl_xor_sync(0xffffffffu, vals[r], off);
        if (lane == 0)
#pragma unroll
            for (int r = 0; r < 9; r++) swarp[wid][r] = vals[r];
        __syncthreads();
        if (tid < 9) {
            float s = 0.f;
            for (int q = 0; q < 32; q++) s += swarp[q][tid];
            sres[tid] = s;
        }
        __syncthreads();

        const float Zt = sres[0];
        if (tid < DDIM) {
            float s = 0.f;
#pragma unroll
            for (int e = 0; e < 8; e++)
                s += Wd[(c * DDIM + tid) * 8 + e] * (sres[1 + e] / Zt);
            sv16[tid] = s;
        }
        __syncthreads();
        if (tid == 0) {
            float sq = 0.f;
#pragma unroll
            for (int d = 0; d < DDIM; d++) sq += sv16[d] * sv16[d];
            sscale = (sq / (1.f + sq)) * rsqrtf(sq + 1e-8f);
        }
        __syncthreads();
        if (tid < DDIM) {
            float vd = sv16[tid] * sscale;
            sv16[tid] = vd;
            if (it == 2) g_v[bc * DDIM + tid] = vd;
        }
        __syncthreads();
        if (it < 2) {
            if (tid < CAP_DIM) {
                float acc = 0.f;
#pragma unroll
                for (int d = 0; d < DDIM; d++)
                    acc += Wd[(c * DDIM + d) * 8 + tid] * sv16[d];
                swv[tid] += acc;
            }
            __syncthreads();
            w0 = swv[0]; w1 = swv[1]; w2v = swv[2]; w3 = swv[3];
            w4 = swv[4]; w5 = swv[5]; w6 = swv[6]; w7 = swv[7];
            __syncthreads();
        }
    }
}

// ---------------- decoder: dec1 builds mask + writes y_ohe/v_len -----------
__global__ __launch_bounds__(256) void dec1_kernel(
    const float* __restrict__ w, const float* __restrict__ bias,
    float* __restrict__ out)
{
    const int tid = threadIdx.x;
    int g = blockIdx.x * 256 + tid;
    int b = g >> 9, j = g & 511;
    __shared__ float sm[160];
    __shared__ float svl[NCLASS];
    __shared__ int spred;
    if (tid < NCLASS) {
        float sq = 0.f;
#pragma unroll
        for (int d = 0; d < DDIM; d++) {
            float vv = g_v[(b * NCLASS + tid) * DDIM + d];
            sq += vv * vv;
        }
        svl[tid] = sq;
    }
    __syncthreads();
    if (tid == 0) {
        int pm = 0; float best = svl[0];
        for (int c = 1; c < NCLASS; c++)
            if (svl[c] > best) { best = svl[c]; pm = c; }
        spred = pm;
    }
    __syncthreads();
    // even block of each batch also emits y_ohe + v_len (finalize merged)
    if (!(blockIdx.x & 1) && tid < NCLASS) {
        out[OUT_Y_OFF + b * NCLASS + tid] = (tid == spred) ? 1.0f : 0.0f;
        out[OUT_VL_OFF + b * NCLASS + tid] = sqrtf(svl[tid]);
    }
    if (tid < 160) {
        int c = tid >> 4, d = tid & 15;
        sm[tid] = (c == spred) ? g_v[(b * NCLASS + c) * DDIM + d] : 0.f;
    }
    __syncthreads();

    float acc = bias[j];
#pragma unroll 8
    for (int i = 0; i < 160; i++)
        acc += sm[i] * w[i * H1N + j];
    g_h1[g] = fmaxf(acc, 0.f);
}

__global__ __launch_bounds__(256) void dec2_kernel(
    const float* __restrict__ w, const float* __restrict__ bias)
{
    int g = blockIdx.x * 256 + threadIdx.x;
    int b = g >> 10, j = g & 1023;
    float acc = bias[j];
#pragma unroll 8
    for (int i = 0; i < H1N; i++)
        acc += g_h1[b * H1N + i] * w[i * H2N + j];
    g_h2[g] = fmaxf(acc, 0.f);
}

__global__ __launch_bounds__(256) void dec3_kernel(
    const float* __restrict__ w, const float* __restrict__ bias,
    float* __restrict__ out)
{
    int jl = threadIdx.x >> 4, b = threadIdx.x & 15;
    int j = blockIdx.x * 16 + jl;
    float acc = bias[j];
#pragma unroll 8
    for (int i = 0; i < H2N; i++)
        acc += g_h2[b * H2N + i] * w[i * RECN + j];
    out[OUT_REC_OFF + b * RECN + j] = 1.f / (1.f + expf(-acc));
}

// ---------------- launch ----------------
extern "C" void kernel_launch(void* const* d_in, const int* in_sizes, int n_in,
                              void* d_out, int out_size)
{
    const float* imgs    = (const float*)d_in[0];
    const float* conv1_w = (const float*)d_in[1];
    const float* conv1_b = (const float*)d_in[2];
    const float* pconv_w = (const float*)d_in[3];
    const float* pconv_b = (const float*)d_in[4];
    const float* W_digit = (const float*)d_in[5];
    const float* dec_w1  = (const float*)d_in[6];
    const float* dec_b1  = (const float*)d_in[7];
    const float* dec_w2  = (const float*)d_in[8];
    const float* dec_b2  = (const float*)d_in[9];
    const float* dec_w3  = (const float*)d_in[10];
    const float* dec_b3  = (const float*)d_in[11];
    float* out = (float*)d_out;

    const int smem_p = NST * STG;
    cudaFuncSetAttribute(pconv_mma_kernel,
                         cudaFuncAttributeMaxDynamicSharedMemorySize, smem_p);
    const int smem_c1 = A1_BYTES + B1_BYTES;
    cudaFuncSetAttribute(conv1_mma_kernel,
                         cudaFuncAttributeMaxDynamicSharedMemorySize, smem_c1);

    wprep_kernel<<<(F2 * KTOT / 4 + 255) / 256, 256>>>(pconv_w, conv1_w, imgs);
    conv1_mma_kernel<<<N1TOT / 64, 256, smem_c1>>>(conv1_b);
    pconv_mma_kernel<<<dim3(NTOT / 64, KSPLIT), 256, smem_p>>>();
    usquash_kernel<<<(BATCH * PP / 4 + 255) / 256, 256>>>(pconv_b);

    routing_all<<<BATCH * NCLASS, 1024>>>(W_digit);

    dec1_kernel<<<(BATCH * H1N) / 256, 256>>>(dec_w1, dec_b1, out);
    dec2_kernel<<<(BATCH * H2N) / 256, 256>>>(dec_w2, dec_b2);
    dec3_kernel<<<RECN / 16, 256>>>(dec_w3, dec_b3, out);
}